// round 3
// baseline (speedup 1.0000x reference)
#include <cuda_runtime.h>

#define N_NODES 100000
#define E_EDGES 3200000
#define D_IN   512
#define D_H    128
#define D_O    64
#define NEG_SLOPE 0.01f

// ---------------- scratch (device globals; no allocation allowed) ----------------
__device__ float g_h1 [N_NODES * D_H];   // 51.2 MB
__device__ float g_h2 [N_NODES * D_O];   // 25.6 MB
__device__ float g_u  [N_NODES * D_O];   // 25.6 MB  (t * dinv, pre-scaled messages)
__device__ float g_acc[N_NODES * D_O];   // 25.6 MB
__device__ float g_h3 [N_NODES * D_O];   // 25.6 MB
__device__ float g_deg [N_NODES];
__device__ float g_dinv[N_NODES];

__device__ __forceinline__ float lrelu(float v) {
    return v >= 0.0f ? v : NEG_SLOPE * v;
}

// ---------------- fp32 SGEMM, 8x8 register tiles, single column-block (N == BN) ----------------
// SCALE_DINV: multiply each output row by g_dinv[row] in the epilogue (u = t * dinv)
template<int BM, int BN, int BK, bool RELU, bool ADD_BIAS, bool SCALE_DINV>
__global__ void gemm_kernel(const float* __restrict__ A,
                            const float* __restrict__ B,
                            const float* __restrict__ bias,
                            float* __restrict__ C,
                            int M, int K) {
    constexpr int TM = 8, TN = 8;
    constexpr int TX = BN / TN;
    constexpr int TY = BM / TM;
    constexpr int THREADS = TX * TY;
    constexpr int KC = BK / 4;              // float4 chunks per A row slice
    constexpr int L4A = BM * BK / (4 * THREADS);
    constexpr int L4B = BK * BN / (4 * THREADS);

    __shared__ float As[BK][BM];
    __shared__ float Bs[BK][BN];

    const int tid  = threadIdx.x;
    const int tx   = tid % TX;
    const int ty   = tid / TX;
    const int row0 = blockIdx.x * BM;

    float acc[TM][TN];
#pragma unroll
    for (int i = 0; i < TM; i++)
#pragma unroll
        for (int j = 0; j < TN; j++) acc[i][j] = 0.0f;

    for (int k0 = 0; k0 < K; k0 += BK) {
        // load A tile (BM x BK), stored transposed As[k][m]
#pragma unroll
        for (int l = 0; l < L4A; l++) {
            int li = tid + l * THREADS;
            int r  = li / KC;
            int kc = li % KC;
            float4 f = make_float4(0.f, 0.f, 0.f, 0.f);
            int gr = row0 + r;
            if (gr < M)
                f = *(const float4*)&A[(long long)gr * K + k0 + kc * 4];
            As[kc * 4 + 0][r] = f.x;
            As[kc * 4 + 1][r] = f.y;
            As[kc * 4 + 2][r] = f.z;
            As[kc * 4 + 3][r] = f.w;
        }
        // load B tile (BK x BN)
#pragma unroll
        for (int l = 0; l < L4B; l++) {
            int li = tid + l * THREADS;
            int r  = li / (BN / 4);
            int c  = li % (BN / 4);
            *(float4*)&Bs[r][c * 4] =
                *(const float4*)&B[(long long)(k0 + r) * BN + c * 4];
        }
        __syncthreads();

#pragma unroll
        for (int kk = 0; kk < BK; kk++) {
            float ra[TM], rb[TN];
#pragma unroll
            for (int i = 0; i < TM; i += 4)
                *(float4*)&ra[i] = *(float4*)&As[kk][ty * TM + i];
#pragma unroll
            for (int j = 0; j < TN; j += 4)
                *(float4*)&rb[j] = *(float4*)&Bs[kk][tx * TN + j];
#pragma unroll
            for (int i = 0; i < TM; i++)
#pragma unroll
                for (int j = 0; j < TN; j++)
                    acc[i][j] += ra[i] * rb[j];
        }
        __syncthreads();
    }

#pragma unroll
    for (int i = 0; i < TM; i++) {
        int gr = row0 + ty * TM + i;
        if (gr >= M) continue;
        float sc = 1.0f;
        if (SCALE_DINV) sc = g_dinv[gr];
#pragma unroll
        for (int j = 0; j < TN; j += 4) {
            float4 v = *(float4*)&acc[i][j];
            int gc = tx * TN + j;
            if (ADD_BIAS) {
                v.x += bias[gc + 0]; v.y += bias[gc + 1];
                v.z += bias[gc + 2]; v.w += bias[gc + 3];
            }
            if (SCALE_DINV) {
                v.x *= sc; v.y *= sc; v.z *= sc; v.w *= sc;
            }
            if (RELU) {
                v.x = lrelu(v.x); v.y = lrelu(v.y);
                v.z = lrelu(v.z); v.w = lrelu(v.w);
            }
            *(float4*)&C[(long long)gr * BN + gc] = v;
        }
    }
}

// ---------------- degree / normalization ----------------
__global__ void init_deg_kernel() {
    int i = blockIdx.x * blockDim.x + threadIdx.x;
    if (i < N_NODES) g_deg[i] = 1.0f;           // self-loop
}

__global__ void count_deg_kernel(const int* __restrict__ dst) {
    int e = blockIdx.x * blockDim.x + threadIdx.x;
    if (e < E_EDGES) atomicAdd(&g_deg[dst[e]], 1.0f);
}

__global__ void calc_dinv_kernel() {
    int i = blockIdx.x * blockDim.x + threadIdx.x;
    if (i < N_NODES) g_dinv[i] = rsqrtf(g_deg[i]);   // deg >= 1 always
}

// ---------------- edge scatter: acc[d] += u[s]  (u already scaled by dinv[s]) ----------------
// one thread per (edge, float4 chunk): 16 chunks of 4 floats per edge
__global__ void edge_scatter_kernel(const int* __restrict__ src,
                                    const int* __restrict__ dst,
                                    const float* __restrict__ u) {
    long long idx = (long long)blockIdx.x * blockDim.x + threadIdx.x;
    if (idx >= (long long)E_EDGES * 16) return;
    int e = (int)(idx >> 4);
    int c = ((int)idx & 15) << 2;
    int s = __ldg(&src[e]);
    int d = __ldg(&dst[e]);
    float4 v = *(const float4*)&u[(long long)s * D_O + c];
    float* p = &g_acc[(long long)d * D_O + c];
    asm volatile("red.global.add.v4.f32 [%0], {%1,%2,%3,%4};"
                 :: "l"(p), "f"(v.x), "f"(v.y), "f"(v.z), "f"(v.w)
                 : "memory");
}

// ---------------- finalize: out = lrelu(dinv[n]*(acc[n] + u[n]) + b) ----------------
// (u[n]*dinv[n] is exactly the self-loop term t[n]*dinv[n]^2)
__global__ void finalize_kernel(const float* __restrict__ u,
                                const float* __restrict__ bias,
                                float* __restrict__ out) {
    int idx = blockIdx.x * blockDim.x + threadIdx.x;
    if (idx >= N_NODES * 16) return;
    int n = idx >> 4;
    int c = (idx & 15) << 2;
    float di = g_dinv[n];
    float4 a  = *(float4*)&g_acc[(long long)n * D_O + c];
    float4 uv = *(const float4*)&u[(long long)n * D_O + c];
    float4 b  = *(const float4*)&bias[c];
    a.x = lrelu(di * (a.x + uv.x) + b.x);
    a.y = lrelu(di * (a.y + uv.y) + b.y);
    a.z = lrelu(di * (a.z + uv.z) + b.z);
    a.w = lrelu(di * (a.w + uv.w) + b.w);
    *(float4*)&out[(long long)n * D_O + c] = a;
}

// ---------------- classifier: logits = h @ Wc + bc ----------------
__global__ void classifier_kernel(const float* __restrict__ h,
                                  const float* __restrict__ Wc,
                                  const float* __restrict__ bc,
                                  float* __restrict__ out) {
    __shared__ float w[D_O * 2];
    __shared__ float b2s[2];
    if (threadIdx.x < D_O * 2) w[threadIdx.x] = Wc[threadIdx.x];
    if (threadIdx.x < 2) b2s[threadIdx.x] = bc[threadIdx.x];
    __syncthreads();
    int n = blockIdx.x * blockDim.x + threadIdx.x;
    if (n >= N_NODES) return;
    float a0 = b2s[0], a1 = b2s[1];
    const float* hr = h + (long long)n * D_O;
#pragma unroll
    for (int k = 0; k < D_O; k++) {
        float v = hr[k];
        a0 += v * w[k * 2 + 0];
        a1 += v * w[k * 2 + 1];
    }
    out[n * 2 + 0] = a0;
    out[n * 2 + 1] = a1;
}

// ---------------- host launcher ----------------
extern "C" void kernel_launch(void* const* d_in, const int* in_sizes, int n_in,
                              void* d_out, int out_size) {
    const float* x   = (const float*)d_in[0];
    const int*   ei  = (const int*)  d_in[1];
    const float* W1  = (const float*)d_in[2];
    const float* b1  = (const float*)d_in[3];
    const float* W2  = (const float*)d_in[4];
    const float* b2  = (const float*)d_in[5];
    const float* Wg1 = (const float*)d_in[6];
    const float* bg1 = (const float*)d_in[7];
    const float* Wg2 = (const float*)d_in[8];
    const float* bg2 = (const float*)d_in[9];
    const float* Wc  = (const float*)d_in[10];
    const float* bc  = (const float*)d_in[11];
    float* out = (float*)d_out;

    const int* src = ei;
    const int* dst = ei + E_EDGES;

    float *h1, *h2, *u, *h3, *acc;
    cudaGetSymbolAddress((void**)&h1,  g_h1);
    cudaGetSymbolAddress((void**)&h2,  g_h2);
    cudaGetSymbolAddress((void**)&u,   g_u);
    cudaGetSymbolAddress((void**)&h3,  g_h3);
    cudaGetSymbolAddress((void**)&acc, g_acc);

    float* logits = out;                      // [N, 2]
    float* h4     = out + 2 * N_NODES;        // [N, 64]  (final h, also classifier input)

    const int MBLK = (N_NODES + 127) / 128;   // 782

    // degrees / symmetric norm first (gemm epilogues consume g_dinv)
    init_deg_kernel <<<(N_NODES + 255) / 256, 256>>>();
    count_deg_kernel<<<(E_EDGES + 255) / 256, 256>>>(dst);
    calc_dinv_kernel<<<(N_NODES + 255) / 256, 256>>>();

    // encoder
    gemm_kernel<128, 128, 16, true, true, false><<<MBLK, 256>>>(x,  W1, b1, h1, N_NODES, D_IN);
    gemm_kernel<128,  64, 16, true, true, false><<<MBLK, 128>>>(h1, W2, b2, h2, N_NODES, D_H);

    const long long SCAT_THREADS = (long long)E_EDGES * 16;
    const int SCAT_BLOCKS = (int)((SCAT_THREADS + 255) / 256);
    const int FIN_BLOCKS  = (N_NODES * 16 + 255) / 256;
    const size_t ACC_BYTES = (size_t)N_NODES * D_O * sizeof(float);

    // GCN layer 1: h3 = lrelu(dinv*(acc + u) + bg1), u = (h2 @ Wg1) * dinv
    gemm_kernel<128, 64, 16, false, false, true><<<MBLK, 128>>>(h2, Wg1, nullptr, u, N_NODES, D_O);
    cudaMemsetAsync(acc, 0, ACC_BYTES);
    edge_scatter_kernel<<<SCAT_BLOCKS, 256>>>(src, dst, u);
    finalize_kernel<<<FIN_BLOCKS, 256>>>(u, bg1, h3);

    // GCN layer 2 -> h4 straight into d_out
    gemm_kernel<128, 64, 16, false, false, true><<<MBLK, 128>>>(h3, Wg2, nullptr, u, N_NODES, D_O);
    cudaMemsetAsync(acc, 0, ACC_BYTES);
    edge_scatter_kernel<<<SCAT_BLOCKS, 256>>>(src, dst, u);
    finalize_kernel<<<FIN_BLOCKS, 256>>>(u, bg2, h4);

    // classifier
    classifier_kernel<<<(N_NODES + 255) / 256, 256>>>(h4, Wc, bc, logits);
}